// round 10
// baseline (speedup 1.0000x reference)
#include <cuda_runtime.h>
#include <cuda_fp16.h>
#include <cstdint>

// ===========================================================================
// MaskedCouplingRQS — Round 10: fp16 m16n8k16, warp grid = 4 rowgroups x
// 2 n-groups (W reads halved), column-major conflict-free P epilogue with
// warp-per-dim task assignment.
// ===========================================================================

#define THREADS 256
#define SA_H 160                      // A stride (halves)
#define SW_H 96                       // W stride (halves)
#define SRP  132                      // P column stride (floats), 132%32=4

// ---- smem byte offsets ----
#define A_B    0                      // 128*160*2 = 40960
#define WA_B   40960                  // 128*96*2  = 24576
#define WB_B   65536                  // 24576
#define P_B    90112                  // 104*132*4 = 54912
#define B1_B   145024
#define B2_B   145536
#define B3_B   146048
#define B4_B   146560                 // 800*4
#define LD_B   149760                 // 4*128*4 = 2048
#define SMEM_BYTES 151808

// ---- packed fp16 weights ----
#define WPK_W1 0                      // 128 rows x 32 halves
#define WPK_W2 4096                   // k0 [128][64], k1 [128][64]
#define WPK_W3 20480
#define WPK_W4 36864                  // 8 x (k0 [104][64], k1 [104][64])
#define W4_CH  13312
#define WPK_TOT 143360
__device__ __half g_wpk[WPK_TOT];

// --------------------------- helpers ---------------------------------------
__device__ __forceinline__ void cp16(void* dst, const void* src) {
    uint32_t s = (uint32_t)__cvta_generic_to_shared(dst);
    asm volatile("cp.async.cg.shared.global [%0], [%1], 16;" :: "r"(s), "l"(src));
}
__device__ __forceinline__ void cp_commit() { asm volatile("cp.async.commit_group;"); }
template<int N>
__device__ __forceinline__ void cp_wait() {
    asm volatile("cp.async.wait_group %0;" :: "n"(N) : "memory");
}
__device__ __forceinline__ void mma16(float* c, uint32_t a0, uint32_t a1,
                                      uint32_t a2, uint32_t a3,
                                      uint32_t b0, uint32_t b1) {
    asm volatile(
        "mma.sync.aligned.m16n8k16.row.col.f32.f16.f16.f32 "
        "{%0,%1,%2,%3}, {%4,%5,%6,%7}, {%8,%9}, {%0,%1,%2,%3};"
        : "+f"(c[0]), "+f"(c[1]), "+f"(c[2]), "+f"(c[3])
        : "r"(a0), "r"(a1), "r"(a2), "r"(a3), "r"(b0), "r"(b1));
}
__device__ __forceinline__ float softplus_f(float v) {
    return fmaxf(v, 0.f) + __logf(1.f + __expf(-fabsf(v)));
}
__device__ __forceinline__ int hpos(int k) {        // packed A/W column position
    int rel = k & 31;
    return ((k >> 5) << 5) + (((rel >> 1) & 3) << 3) + ((rel >> 3) << 1) + (rel & 1);
}

// ---------------------------------------------------------------------------
// prep: pack all weights to fp16, mma-native column order (R9-verified map).
// At packed pos p in a 64-col row: kg=p>>5, rem=p&31, m=rem>>3, h=rem&7
//   -> k = kg*32 + 2m + (h&1) + 8*(h>>1)
// ---------------------------------------------------------------------------
__global__ void prep_weights(const float* __restrict__ W1, const float* __restrict__ W2,
                             const float* __restrict__ W3, const float* __restrict__ W4)
{
    int idx = blockIdx.x * blockDim.x + threadIdx.x;
    if (idx >= WPK_TOT) return;
    float v;
    if (idx < WPK_W2) {                               // W1: 128 x 32 halves
        int n = idx >> 5, p = idx & 31;
        int mm = p >> 3, hh = p & 7;
        int k = 2 * mm + (hh & 1) + 8 * (hh >> 1);
        v = W1[n * 32 + k];
    } else if (idx < WPK_W4) {                        // W2/W3: k0 then k1, [128][64]
        int t = idx - WPK_W2;
        const float* W = (t < 16384) ? W2 : W3;
        int r = t & 16383;
        int kh = r >> 13, rr = r & 8191;
        int n = rr >> 6, p = rr & 63;
        int kg = p >> 5, rem = p & 31, mm = rem >> 3, hh = rem & 7;
        int kl = kg * 32 + 2 * mm + (hh & 1) + 8 * (hh >> 1);
        v = W[n * 128 + kh * 64 + kl];
    } else {                                          // W4: 8 x (k0,k1) [104][64]
        int t = idx - WPK_W4;
        int c = t / W4_CH, r = t - c * W4_CH;
        int kh = (r >= 6656) ? 1 : 0;
        int rr = kh ? r - 6656 : r;
        int n = rr >> 6, p = rr & 63;
        int kg = p >> 5, rem = p & 31, mm = rem >> 3, hh = rem & 7;
        int kl = kg * 32 + 2 * mm + (hh & 1) + 8 * (hh >> 1);
        v = (n < 100) ? W4[(size_t)(c * 100 + n) * 128 + kh * 64 + kl] : 0.f;
    }
    g_wpk[idx] = __float2half_rn(v);
}

// ---------------------------------------------------------------------------
template<int ROWH>
__device__ __forceinline__ void stage_u(__half* dst, const __half* src, int nrows) {
    constexpr int CH = ROWH / 8;
    for (int i = threadIdx.x; i < nrows * CH; i += THREADS) {
        int row = i / CH, j = i - row * CH;
        cp16(dst + row * SW_H + j * 8, src + row * ROWH + j * 8);
    }
}

// MMA over one staged k-half unit; 2 m-tiles per warp.
template<int NT, int KG>
__device__ __forceinline__ void mma_unit2(const __half* a0p, const __half* a1p,
                                          const __half* Wg, float* C) {
    #pragma unroll
    for (int kg = 0; kg < KG; kg++) {
        uint4 X0 = *(const uint4*)(a0p + kg * 32);
        uint4 Y0 = *(const uint4*)(a0p + 8 * SA_H + kg * 32);
        uint4 X1 = *(const uint4*)(a1p + kg * 32);
        uint4 Y1 = *(const uint4*)(a1p + 8 * SA_H + kg * 32);
        #pragma unroll
        for (int nt = 0; nt < NT; nt++) {
            uint4 Wv = *(const uint4*)(Wg + nt * 8 * SW_H + kg * 32);
            mma16(C + nt * 8,     X0.x, Y0.x, X0.y, Y0.y, Wv.x, Wv.y);
            mma16(C + nt * 8,     X0.z, Y0.z, X0.w, Y0.w, Wv.z, Wv.w);
            mma16(C + nt * 8 + 4, X1.x, Y1.x, X1.y, Y1.y, Wv.x, Wv.y);
            mma16(C + nt * 8 + 4, X1.z, Y1.z, X1.w, Y1.w, Wv.z, Wv.w);
        }
    }
}

// relu(C + bias) -> packed fp16 A (own 32 rows x own 64-col half)
__device__ __forceinline__ void relu_store2(const float* C, const float* bs,
                                            __half* Ah, int R0, int ng) {
    const int lane = threadIdx.x & 31;
    const int g = lane >> 2, m = lane & 3;
    #pragma unroll
    for (int mt = 0; mt < 2; mt++) {
        const int rb = R0 + mt * 16;
        #pragma unroll
        for (int nt = 0; nt < 8; nt++) {
            const int ntg = nt + ng * 8;
            const int c0 = ntg * 8 + 2 * m;
            const float b0 = bs[c0], b1 = bs[c0 + 1];
            const int off = ((ntg >> 2) << 5) + (m << 3) + ((ntg & 3) << 1);
            const float* Cc = C + nt * 8 + mt * 4;
            *(__half2*)(Ah + (rb + g) * SA_H + off) =
                __floats2half2_rn(fmaxf(Cc[0] + b0, 0.f), fmaxf(Cc[1] + b1, 0.f));
            *(__half2*)(Ah + (rb + g + 8) * SA_H + off) =
                __floats2half2_rn(fmaxf(Cc[2] + b0, 0.f), fmaxf(Cc[3] + b1, 0.f));
        }
    }
}

// column-major P store: P[col*SRP + row]; banks 8m+g -> conflict-free
template<int NT>
__device__ __forceinline__ void p_store2(const float* C, float* P, int R0, int ng) {
    const int lane = threadIdx.x & 31;
    const int g = lane >> 2, m = lane & 3;
    #pragma unroll
    for (int mt = 0; mt < 2; mt++) {
        const int rb = R0 + mt * 16;
        #pragma unroll
        for (int nt = 0; nt < NT; nt++) {
            const int c0 = ng * 64 + nt * 8 + 2 * m;
            const float* Cc = C + nt * 8 + mt * 4;
            P[c0 * SRP + rb + g]           = Cc[0];
            P[(c0 + 1) * SRP + rb + g]     = Cc[1];
            P[c0 * SRP + rb + g + 8]       = Cc[2];
            P[(c0 + 1) * SRP + rb + g + 8] = Cc[3];
        }
    }
}

// ---------------------------------------------------------------------------
__global__ __launch_bounds__(THREADS, 1)
void rqs_mma_kernel(const float* __restrict__ x,
                    const float* __restrict__ b1, const float* __restrict__ b2,
                    const float* __restrict__ b3, const float* __restrict__ b4,
                    float* __restrict__ out, int B)
{
    extern __shared__ char smem[];
    __half* Ah  = (__half*)(smem + A_B);
    __half* WAb = (__half*)(smem + WA_B);
    __half* WBb = (__half*)(smem + WB_B);
    float*  Psm = (float*)(smem + P_B);
    float*  B1S = (float*)(smem + B1_B);
    float*  B2S = (float*)(smem + B2_B);
    float*  B3S = (float*)(smem + B3_B);
    float*  B4S = (float*)(smem + B4_B);
    float*  LDA = (float*)(smem + LD_B);

    const int tid  = threadIdx.x;
    const int lane = tid & 31;
    const int g    = lane >> 2, m = lane & 3;
    const int warp = tid >> 5;
    const int rg   = warp & 3;            // rowgroup (32 rows)  / epilogue dim
    const int ng   = warp >> 2;           // n-group             / epilogue rowblk
    const int R0   = rg * 32;
    const long row0 = (long)blockIdx.x * 128;

    const __half* aw0 = Ah + (R0 + g) * SA_H + m * 8;
    const __half* aw1 = aw0 + 16 * SA_H;
    const __half* WAg = WAb + (ng * 64 + g) * SW_H + m * 8;
    const __half* WBg = WBb + (ng * 64 + g) * SW_H + m * 8;
    const __half* gw  = g_wpk;

    // ---- g0: W1 + biases -> WA ; g1: W2k0 -> WB ----
    stage_u<32>(WAb, gw + WPK_W1, 128);
    for (int i = tid; i < 32; i += THREADS) {
        cp16(B1S + i * 4, b1 + i * 4);
        cp16(B2S + i * 4, b2 + i * 4);
        cp16(B3S + i * 4, b3 + i * 4);
    }
    for (int i = tid; i < 200; i += THREADS) cp16(B4S + i * 4, b4 + i * 4);
    cp_commit();
    stage_u<64>(WBb, gw + WPK_W2, 128); cp_commit();

    // ---- x_masked -> packed fp16 A ----
    for (int i = tid; i < 1024; i += THREADS) {
        int row = i >> 3, j = i & 7;
        float4 v = make_float4(0.f, 0.f, 0.f, 0.f);
        if (row0 + row < B) v = *(const float4*)(x + (row0 + row) * 64 + j * 4);
        __half* Ar = Ah + row * SA_H;
        Ar[hpos(j * 4 + 0)] = __float2half_rn(v.x);
        Ar[hpos(j * 4 + 1)] = __float2half_rn(v.y);
        Ar[hpos(j * 4 + 2)] = __float2half_rn(v.z);
        Ar[hpos(j * 4 + 3)] = __float2half_rn(v.w);
    }

    cp_wait<1>(); __syncthreads();

    float C[64];

    // ================= Layer 1 (K=32) =================
    #pragma unroll
    for (int i = 0; i < 64; i++) C[i] = 0.f;
    mma_unit2<8, 1>(aw0, aw1, WAg, C);
    __syncthreads(); stage_u<64>(WAb, gw + WPK_W2 + 8192, 128); cp_commit();   // W2k1
    relu_store2(C, B1S, Ah, R0, ng);                                           // h1

    // ================= Layer 2 =================
    #pragma unroll
    for (int i = 0; i < 64; i++) C[i] = 0.f;
    cp_wait<1>(); __syncthreads();
    mma_unit2<8, 2>(aw0, aw1, WBg, C);                                         // k0
    __syncthreads(); stage_u<64>(WBb, gw + WPK_W3, 128); cp_commit();          // W3k0
    cp_wait<1>(); __syncthreads();
    mma_unit2<8, 2>(aw0 + 64, aw1 + 64, WAg, C);                               // k1
    __syncthreads(); stage_u<64>(WAb, gw + WPK_W3 + 8192, 128); cp_commit();   // W3k1
    relu_store2(C, B2S, Ah, R0, ng);                                           // h2

    // ================= Layer 3 =================
    #pragma unroll
    for (int i = 0; i < 64; i++) C[i] = 0.f;
    cp_wait<1>(); __syncthreads();
    mma_unit2<8, 2>(aw0, aw1, WBg, C);
    __syncthreads(); stage_u<64>(WBb, gw + WPK_W4, 104); cp_commit();          // c0 k0
    cp_wait<1>(); __syncthreads();
    mma_unit2<8, 2>(aw0 + 64, aw1 + 64, WAg, C);
    __syncthreads(); stage_u<64>(WAb, gw + WPK_W4 + 6656, 104); cp_commit();   // c0 k1
    relu_store2(C, B3S, Ah, R0, ng);                                           // h3

    // ================= Layer 4 + spline, 8 chunks =================
    const float MINB = 1e-4f;
    const float FREE = 10.f - 8.f * 1e-4f;
    float ld0 = 0.f, ld1 = 0.f;

    #pragma unroll 1
    for (int c = 0; c < 8; c++) {
        const __half* nk = gw + WPK_W4 + (c + 1) * W4_CH;

        #pragma unroll
        for (int i = 0; i < 64; i++) C[i] = 0.f;

        cp_wait<1>(); __syncthreads();                 // k0 in WB; prev P reads done
        if (ng == 0) mma_unit2<8, 2>(aw0, aw1, WBg, C);
        else         mma_unit2<5, 2>(aw0, aw1, WBg, C);
        __syncthreads();
        if (c < 7) { stage_u<64>(WBb, nk, 104); cp_commit(); }          // next k0
        if (c < 7) { cp_wait<1>(); } else { cp_wait<0>(); }
        __syncthreads();                               // k1 in WA
        if (ng == 0) mma_unit2<8, 2>(aw0 + 64, aw1 + 64, WAg, C);
        else         mma_unit2<5, 2>(aw0 + 64, aw1 + 64, WAg, C);
        __syncthreads();
        if (c < 7) { stage_u<64>(WAb, nk + 6656, 104); cp_commit(); }   // next k1
        if (ng == 0) p_store2<8>(C, Psm, R0, 0);
        else         p_store2<5>(C, Psm, R0, 1);
        __syncthreads();

        // -------- epilogue: warp handles dim rg, rows (ng+2s)*32+lane --------
        #pragma unroll
        for (int s = 0; s < 2; s++) {
            const int row = (ng + 2 * s) * 32 + lane;
            const int t   = c * 4 + rg;

            float acc[25];
            #pragma unroll
            for (int p = 0; p < 25; p++)
                acc[p] = Psm[(rg * 25 + p) * SRP + row] + B4S[c * 100 + rg * 25 + p];

            float mx = acc[0];
            #pragma unroll
            for (int i = 1; i < 8; i++) mx = fmaxf(mx, acc[i]);
            float wdt[8]; float Sw = 0.f;
            #pragma unroll
            for (int i = 0; i < 8; i++) { wdt[i] = __expf(acc[i] - mx); Sw += wdt[i]; }
            float mh = acc[8];
            #pragma unroll
            for (int i = 9; i < 16; i++) mh = fmaxf(mh, acc[i]);
            float hgt[8]; float Sh = 0.f;
            #pragma unroll
            for (int i = 0; i < 8; i++) { hgt[i] = __expf(acc[8 + i] - mh); Sh += hgt[i]; }
            const float fw = FREE / Sw, fh = FREE / Sh;
            #pragma unroll
            for (int i = 0; i < 8; i++) {
                wdt[i] = MINB + wdt[i] * fw;
                hgt[i] = MINB + hgt[i] * fh;
            }

            float xt = 0.f;
            const bool vr = (row0 + row) < B;
            if (vr) xt = x[(row0 + row) * 64 + 32 + t];
            const float xc = fminf(fmaxf(xt, -5.f), 5.f);
            const bool inside = (xt >= -5.f) && (xt <= 5.f);

            int idx = 0; float cum = -5.f, xk = -5.f, wk = wdt[0];
            #pragma unroll
            for (int i = 0; i < 7; i++) {
                cum += wdt[i];
                if (xc >= cum) { idx = i + 1; xk = cum; wk = wdt[i + 1]; }
            }
            float cumh = -5.f, yk = -5.f, hk = hgt[0];
            #pragma unroll
            for (int i = 0; i < 7; i++) {
                cumh += hgt[i];
                if (idx > i) { yk = cumh; hk = hgt[i + 1]; }
            }
            float sA = acc[16], sB = acc[17];
            #pragma unroll
            for (int i = 1; i < 8; i++)
                if (idx >= i) { sA = acc[16 + i]; sB = acc[17 + i]; }
            const float dk  = 1e-4f + softplus_f(sA);
            const float dk1 = 1e-4f + softplus_f(sB);

            const float rwk  = 1.f / wk;
            const float xi   = (xc - xk) * rwk;
            const float om   = 1.f - xi;
            const float sk   = hk * rwk;
            const float xiom = xi * om;
            const float den  = sk + (dk1 + dk - 2.f * sk) * xiom;
            const float rden = 1.f / den;
            const float num  = sk * xi * xi + dk * xiom;
            const float y_in = yk + hk * num * rden;
            const float num2 = dk1 * xi * xi + 2.f * sk * xiom + dk * om * om;
            const float ld_in = __logf(sk * sk * num2 * rden * rden);

            if (vr) out[(row0 + row) * 64 + 32 + t] = inside ? y_in : xt;
            const float ldv = inside ? ld_in : 0.f;
            if (s == 0) ld0 += ldv; else ld1 += ldv;
        }
    }

    // ---- logdet: 4 dim-partials per row via smem ----
    LDA[rg * 128 + ng * 32 + lane]       = ld0;
    LDA[rg * 128 + (ng + 2) * 32 + lane] = ld1;
    __syncthreads();
    if (tid < 128) {
        float v = LDA[tid] + LDA[128 + tid] + LDA[256 + tid] + LDA[384 + tid];
        if (row0 + tid < B) out[(size_t)B * 64 + row0 + tid] = v;
    }

    // ---- masked-column copy ----
    for (int i = tid; i < 1024; i += THREADS) {
        int row = i >> 3, j = i & 7;
        if (row0 + row < B)
            *(float4*)(out + (row0 + row) * 64 + j * 4) =
                *(const float4*)(x + (row0 + row) * 64 + j * 4);
    }
}

// ---------------------------------------------------------------------------
extern "C" void kernel_launch(void* const* d_in, const int* in_sizes, int n_in,
                              void* d_out, int out_size)
{
    const float* x  = (const float*)d_in[0];
    const float* W1 = (const float*)d_in[1];
    const float* b1 = (const float*)d_in[2];
    const float* W2 = (const float*)d_in[3];
    const float* b2 = (const float*)d_in[4];
    const float* W3 = (const float*)d_in[5];
    const float* b3 = (const float*)d_in[6];
    const float* W4 = (const float*)d_in[7];
    const float* b4 = (const float*)d_in[8];
    float* out = (float*)d_out;

    const int B = in_sizes[0] / 64;

    prep_weights<<<(WPK_TOT + 255) / 256, 256>>>(W1, W2, W3, W4);

    cudaFuncSetAttribute(rqs_mma_kernel,
                         cudaFuncAttributeMaxDynamicSharedMemorySize, SMEM_BYTES);
    const int grid = (B + 127) / 128;
    rqs_mma_kernel<<<grid, THREADS, SMEM_BYTES>>>(x, b1, b2, b3, b4, out, B);
}